// round 11
// baseline (speedup 1.0000x reference)
#include <cuda_runtime.h>
#include <cuda_bf16.h>

// Problem constants
#define CUR   512
#define HID   64
#define OUTD  64
#define HEADS 6
#define FTOT  (HEADS*OUTD)   // 384
#define CATD  (HID + FTOT)   // 448
#define NMAX  50000
#define EMAX  860000

// ---------------- device scratch ----------------
__device__ float g_h[(size_t)NMAX * HID];        // 12.8 MB (L2 resident)
__device__ float g_acc[(size_t)NMAX * FTOT];     // gathered, normalized
__device__ float g_asrc[(size_t)NMAX * HEADS];
__device__ float g_adst[(size_t)NMAX * HEADS];
__device__ float g_ws[HID * HEADS];              // W_gat_h @ att_src_h
__device__ float g_wd[HID * HEADS];
__device__ int   g_deg[NMAX];
__device__ int   g_cnt[NMAX];
__device__ int   g_off[NMAX + 1];
__device__ int   g_csrc[EMAX];
__device__ int   g_is64;

// ---------------- helpers ----------------
__device__ __forceinline__ void load_edge(const void* eidx, long E, long i,
                                          int& s, int& d) {
    if (g_is64) {
        const long long* p = (const long long*)eidx;
        s = (int)p[i];
        d = (int)p[E + i];
    } else {
        const int* p = (const int*)eidx;
        s = p[i];
        d = p[E + i];
    }
}

// int64 indices < 50000 => all high words zero over first 64 entries.
__global__ void k_detect(const int* e32) {
    int allzero = 1;
    for (int i = 1; i < 128; i += 2)
        if (e32[i] != 0) { allzero = 0; break; }
    g_is64 = allzero;
}

__global__ void k_zero(int nN) {
    int i = blockIdx.x * blockDim.x + threadIdx.x;
    if (i < nN) { g_deg[i] = 0; g_cnt[i] = 0; }
}

// ws[k][h] = sum_c W_gat[k, h*64+c] * att_src[h][c]   (and wd with att_dst)
__global__ void k_wsd(const float* __restrict__ Wg,
                      const float* __restrict__ as_,
                      const float* __restrict__ ad_) {
    int t = threadIdx.x;            // 0..383
    int h = t >> 6, k = t & 63;
    float s = 0.f, d = 0.f;
    #pragma unroll 8
    for (int c = 0; c < OUTD; c++) {
        float wv = Wg[k * FTOT + h * OUTD + c];
        s += wv * as_[h * OUTD + c];
        d += wv * ad_[h * OUTD + c];
    }
    g_ws[k * HEADS + h] = s;
    g_wd[k * HEADS + h] = d;
}

// ---------------- histogram of dst ----------------
__global__ void k_hist(const void* eidx, long E, long E2) {
    long i = (long)blockIdx.x * blockDim.x + threadIdx.x;
    if (i >= E2) return;
    int d;
    if (i < E) {
        if (g_is64) d = (int)((const long long*)eidx)[E + i];
        else        d = ((const int*)eidx)[E + i];
    } else d = (int)(i - E);
    atomicAdd(&g_deg[d], 1);
}

// ---------------- exclusive scan (single block) ----------------
__global__ void k_scan(int nN) {
    __shared__ int part[1024];
    int t = threadIdx.x;
    int chunk = (nN + 1023) / 1024;
    int lo = t * chunk;
    int hi = lo + chunk; if (hi > nN) hi = nN; if (lo > nN) lo = nN;
    int s = 0;
    for (int i = lo; i < hi; i++) s += g_deg[i];
    part[t] = s;
    __syncthreads();
    for (int o = 1; o < 1024; o <<= 1) {
        int v = 0;
        if (t >= o) v = part[t - o];
        __syncthreads();
        if (t >= o) part[t] += v;
        __syncthreads();
    }
    int run = (t > 0) ? part[t - 1] : 0;
    for (int i = lo; i < hi; i++) { g_off[i] = run; run += g_deg[i]; }
    if (t == 1023) g_off[nN] = part[1023];
}

__global__ void k_fill(const void* eidx, long E, long E2) {
    long i = (long)blockIdx.x * blockDim.x + threadIdx.x;
    if (i >= E2) return;
    int s, d;
    if (i < E) load_edge(eidx, E, i, s, d);
    else       s = d = (int)(i - E);
    int pos = g_off[d] + atomicAdd(&g_cnt[d], 1);
    g_csrc[pos] = s;
}

// ---------------- h = x @ W_pre + b_pre ----------------
// block (32,4): each thread 2 cols x 4 rows; 16 rows/block
__global__ void __launch_bounds__(128, 4)
k_pre(const float* __restrict__ x, const float* __restrict__ W,
      const float* __restrict__ b, int nN) {
    __shared__ float xs[16][CUR];
    int tx = threadIdx.x, ty = threadIdx.y;
    int tid = ty * 32 + tx;
    int row0 = blockIdx.x * 16;
    float4* xsv = (float4*)&xs[0][0];
    const int VROW = CUR / 4;  // 128
    for (int i = tid; i < 16 * VROW; i += 128) {
        int r = i / VROW, q = i % VROW;
        int rr = row0 + r;
        float4 v = make_float4(0.f, 0.f, 0.f, 0.f);
        if (rr < nN) v = ((const float4*)(x + (size_t)rr * CUR))[q];
        xsv[i] = v;
    }
    __syncthreads();
    int c0 = tx * 2;
    float a00 = 0.f, a01 = 0.f, a10 = 0.f, a11 = 0.f;
    float a20 = 0.f, a21 = 0.f, a30 = 0.f, a31 = 0.f;
    int r0 = ty * 4;
    #pragma unroll 2
    for (int k = 0; k < CUR; k += 4) {
        float2 w0 = *(const float2*)&W[(k + 0) * HID + c0];
        float2 w1 = *(const float2*)&W[(k + 1) * HID + c0];
        float2 w2 = *(const float2*)&W[(k + 2) * HID + c0];
        float2 w3 = *(const float2*)&W[(k + 3) * HID + c0];
        float4 v0 = *(float4*)&xs[r0 + 0][k];
        float4 v1 = *(float4*)&xs[r0 + 1][k];
        float4 v2 = *(float4*)&xs[r0 + 2][k];
        float4 v3 = *(float4*)&xs[r0 + 3][k];
        a00 += v0.x * w0.x + v0.y * w1.x + v0.z * w2.x + v0.w * w3.x;
        a01 += v0.x * w0.y + v0.y * w1.y + v0.z * w2.y + v0.w * w3.y;
        a10 += v1.x * w0.x + v1.y * w1.x + v1.z * w2.x + v1.w * w3.x;
        a11 += v1.x * w0.y + v1.y * w1.y + v1.z * w2.y + v1.w * w3.y;
        a20 += v2.x * w0.x + v2.y * w1.x + v2.z * w2.x + v2.w * w3.x;
        a21 += v2.x * w0.y + v2.y * w1.y + v2.z * w2.y + v2.w * w3.y;
        a30 += v3.x * w0.x + v3.y * w1.x + v3.z * w2.x + v3.w * w3.x;
        a31 += v3.x * w0.y + v3.y * w1.y + v3.z * w2.y + v3.w * w3.y;
    }
    float2 bb = *(const float2*)&b[c0];
    int rr = row0 + r0;
    if (rr + 0 < nN) { float2 s = {a00 + bb.x, a01 + bb.y}; *(float2*)&g_h[(size_t)(rr + 0) * HID + c0] = s; }
    if (rr + 1 < nN) { float2 s = {a10 + bb.x, a11 + bb.y}; *(float2*)&g_h[(size_t)(rr + 1) * HID + c0] = s; }
    if (rr + 2 < nN) { float2 s = {a20 + bb.x, a21 + bb.y}; *(float2*)&g_h[(size_t)(rr + 2) * HID + c0] = s; }
    if (rr + 3 < nN) { float2 s = {a30 + bb.x, a31 + bb.y}; *(float2*)&g_h[(size_t)(rr + 3) * HID + c0] = s; }
}

// ---------------- a_src / a_dst from h directly: warp per node ------------
__global__ void k_att2(int nN) {
    int n = blockIdx.x * (blockDim.x >> 5) + (threadIdx.x >> 5);
    if (n >= nN) return;
    int lane = threadIdx.x & 31;
    float h0 = g_h[(size_t)n * HID + lane];
    float h1v = g_h[(size_t)n * HID + 32 + lane];
    float sv[HEADS], dv[HEADS];
    #pragma unroll
    for (int h = 0; h < HEADS; h++) {
        sv[h] = h0 * g_ws[lane * HEADS + h] + h1v * g_ws[(lane + 32) * HEADS + h];
        dv[h] = h0 * g_wd[lane * HEADS + h] + h1v * g_wd[(lane + 32) * HEADS + h];
    }
    #pragma unroll
    for (int o = 16; o > 0; o >>= 1) {
        #pragma unroll
        for (int h = 0; h < HEADS; h++) {
            sv[h] += __shfl_xor_sync(0xffffffffu, sv[h], o);
            dv[h] += __shfl_xor_sync(0xffffffffu, dv[h], o);
        }
    }
    if (lane == 0) {
        #pragma unroll
        for (int h = 0; h < HEADS; h++) {
            g_asrc[n * HEADS + h] = sv[h];
            g_adst[n * HEADS + h] = dv[h];
        }
    }
}

// ---------------- CSR gather of h[src]: softmax-weighted, atomic-free -----
#define GW 8
__global__ void k_gather(int nN) {
    __shared__ float exs[GW][32][HEADS];
    int w = threadIdx.x >> 5;
    int n = blockIdx.x * GW + w;
    if (n >= nN) return;
    int lane = threadIdx.x & 31;
    int lo = g_off[n], hi = g_off[n + 1];

    float adv = (lane < HEADS) ? g_adst[n * HEADS + lane] : 0.f;
    float adn[HEADS];
    #pragma unroll
    for (int h = 0; h < HEADS; h++) adn[h] = __shfl_sync(0xffffffffu, adv, h);

    float mx[HEADS];
    #pragma unroll
    for (int h = 0; h < HEADS; h++) mx[h] = -1e30f;
    for (int j = lo + lane; j < hi; j += 32) {
        int s = g_csrc[j];
        const float2* ap = (const float2*)&g_asrc[s * HEADS];
        float2 a01 = ap[0], a23 = ap[1], a45 = ap[2];
        float av[HEADS] = {a01.x, a01.y, a23.x, a23.y, a45.x, a45.y};
        #pragma unroll
        for (int h = 0; h < HEADS; h++) {
            float a = av[h] + adn[h];
            a = (a > 0.f) ? a : 0.2f * a;
            mx[h] = fmaxf(mx[h], a);
        }
    }
    #pragma unroll
    for (int h = 0; h < HEADS; h++)
        #pragma unroll
        for (int o = 16; o > 0; o >>= 1)
            mx[h] = fmaxf(mx[h], __shfl_xor_sync(0xffffffffu, mx[h], o));

    float acc[2 * HEADS];
    #pragma unroll
    for (int q = 0; q < 2 * HEADS; q++) acc[q] = 0.f;
    float den[HEADS];
    #pragma unroll
    for (int h = 0; h < HEADS; h++) den[h] = 0.f;

    for (int base = lo; base < hi; base += 32) {
        int j = base + lane;
        int s = 0;
        if (j < hi) {
            s = g_csrc[j];
            const float2* ap = (const float2*)&g_asrc[s * HEADS];
            float2 a01 = ap[0], a23 = ap[1], a45 = ap[2];
            float av[HEADS] = {a01.x, a01.y, a23.x, a23.y, a45.x, a45.y};
            #pragma unroll
            for (int h = 0; h < HEADS; h++) {
                float a = av[h] + adn[h];
                a = (a > 0.f) ? a : 0.2f * a;
                float ex = __expf(a - mx[h]);
                den[h] += ex;
                exs[w][lane][h] = ex;
            }
        }
        __syncwarp();
        int cnt = hi - base; if (cnt > 32) cnt = 32;
        for (int e = 0; e < cnt; e++) {
            int se = __shfl_sync(0xffffffffu, s, e);
            float2 hv = ((const float2*)(g_h + (size_t)se * HID))[lane];
            #pragma unroll
            for (int h = 0; h < HEADS; h++) {
                float ex = exs[w][e][h];
                acc[2 * h + 0] += ex * hv.x;
                acc[2 * h + 1] += ex * hv.y;
            }
        }
        __syncwarp();
    }

    #pragma unroll
    for (int h = 0; h < HEADS; h++)
        #pragma unroll
        for (int o = 16; o > 0; o >>= 1)
            den[h] += __shfl_xor_sync(0xffffffffu, den[h], o);

    #pragma unroll
    for (int h = 0; h < HEADS; h++) {
        float inv = 1.f / den[h];
        float2 st;
        st.x = acc[2 * h + 0] * inv;
        st.y = acc[2 * h + 1] * inv;
        ((float2*)(g_acc + (size_t)n * FTOT + h * OUTD))[lane] = st;
    }
}

// ---------------- fused: h1 = leakyrelu(acc@Wg + bg); out = [h,h1]@Wl + bl
__global__ void __launch_bounds__(384, 2)
k_out(const float* __restrict__ Wg, const float* __restrict__ bg,
      const float* __restrict__ Wl, const float* __restrict__ bl,
      float* __restrict__ out, int nN) {
    __shared__ float as[16][FTOT];   // acc tile
    __shared__ float cat[16][CATD];  // [h | h1] tile
    int t = threadIdx.x;             // 0..383
    int row0 = blockIdx.x * 16;

    // stage 1: load acc tile + h tile
    float4* asv = (float4*)&as[0][0];
    const int AV = FTOT / 4;  // 96
    for (int i = t; i < 16 * AV; i += 384) {
        int r = i / AV, q = i % AV;
        int rr = row0 + r;
        float4 v = make_float4(0.f, 0.f, 0.f, 0.f);
        if (rr < nN) v = ((const float4*)(g_acc + (size_t)rr * FTOT))[q];
        asv[i] = v;
    }
    const int HV = HID / 4;   // 16
    for (int i = t; i < 16 * HV; i += 384) {
        int r = i / HV, q = i % HV;
        int rr = row0 + r;
        float4 v = make_float4(0.f, 0.f, 0.f, 0.f);
        if (rr < nN) v = ((const float4*)(g_h + (size_t)rr * HID))[q];
        *(float4*)&cat[r][q * 4] = v;
    }
    __syncthreads();

    // stage 2: h1 col t for 16 rows -> cat[r][HID+t]
    {
        int kb = (t >> 6) * OUTD;   // head offset into acc row
        float bb = bg[t];
        float h1a[16];
        #pragma unroll
        for (int r = 0; r < 16; r++) h1a[r] = 0.f;
        #pragma unroll
        for (int kc = 0; kc < HID; kc += 16) {
            float wreg[16];
            #pragma unroll
            for (int k = 0; k < 16; k++) wreg[k] = Wg[(kc + k) * FTOT + t];
            #pragma unroll
            for (int r = 0; r < 16; r++) {
                #pragma unroll
                for (int k = 0; k < 16; k += 4) {
                    float4 v = *(float4*)&as[r][kb + kc + k];
                    h1a[r] += v.x * wreg[k] + v.y * wreg[k + 1]
                            + v.z * wreg[k + 2] + v.w * wreg[k + 3];
                }
            }
        }
        #pragma unroll
        for (int r = 0; r < 16; r++) {
            float v = h1a[r] + bb;
            cat[r][HID + t] = (v > 0.f) ? v : 0.01f * v;
        }
    }
    __syncthreads();

    // stage 3: out = cat @ Wl + bl; thread t -> col = t&63, rows rg, rg+6, rg+12
    {
        int col = t & 63, rg = t >> 6;
        float ac0 = 0.f, ac1 = 0.f, ac2 = 0.f;
        int r1 = rg + 6, r2 = rg + 12;
        #pragma unroll 4
        for (int k = 0; k < CATD; k += 4) {
            float w0 = Wl[(k + 0) * OUTD + col];
            float w1 = Wl[(k + 1) * OUTD + col];
            float w2 = Wl[(k + 2) * OUTD + col];
            float w3 = Wl[(k + 3) * OUTD + col];
            float4 v0 = *(float4*)&cat[rg][k];
            ac0 += v0.x * w0 + v0.y * w1 + v0.z * w2 + v0.w * w3;
            float4 v1 = *(float4*)&cat[r1][k];
            ac1 += v1.x * w0 + v1.y * w1 + v1.z * w2 + v1.w * w3;
            if (r2 < 16) {
                float4 v2 = *(float4*)&cat[r2][k];
                ac2 += v2.x * w0 + v2.y * w1 + v2.z * w2 + v2.w * w3;
            }
        }
        float bb = bl[col];
        int rr0 = row0 + rg, rr1 = row0 + r1, rr2 = row0 + r2;
        if (rr0 < nN)             out[(size_t)rr0 * OUTD + col] = ac0 + bb;
        if (rr1 < nN)             out[(size_t)rr1 * OUTD + col] = ac1 + bb;
        if (r2 < 16 && rr2 < nN)  out[(size_t)rr2 * OUTD + col] = ac2 + bb;
    }
}

// ---------------- launch ----------------
extern "C" void kernel_launch(void* const* d_in, const int* in_sizes, int n_in,
                              void* d_out, int out_size) {
    const float* x    = (const float*)d_in[0];
    const void*  eidx = d_in[1];
    const float* Wpre = (const float*)d_in[3];
    const float* bpre = (const float*)d_in[4];
    const float* Wgat = (const float*)d_in[5];
    const float* atts = (const float*)d_in[6];
    const float* attd = (const float*)d_in[7];
    const float* bgat = (const float*)d_in[8];
    const float* Wlin = (const float*)d_in[9];
    const float* blin = (const float*)d_in[10];
    float* out = (float*)d_out;

    int  nN = in_sizes[0] / CUR;
    long E  = (long)in_sizes[1] / 2;
    long E2 = E + nN;

    k_detect<<<1, 1>>>((const int*)eidx);
    k_zero<<<(nN + 255) / 256, 256>>>(nN);
    k_wsd<<<1, 384>>>(Wgat, atts, attd);
    k_pre<<<(nN + 15) / 16, dim3(32, 4)>>>(x, Wpre, bpre, nN);
    k_att2<<<(nN + 7) / 8, 256>>>(nN);
    k_hist<<<(int)((E2 + 255) / 256), 256>>>(eidx, E, E2);
    k_scan<<<1, 1024>>>(nN);
    k_fill<<<(int)((E2 + 255) / 256), 256>>>(eidx, E, E2);
    k_gather<<<(nN + GW - 1) / GW, GW * 32>>>(nN);
    k_out<<<(nN + 15) / 16, 384>>>(Wgat, bgat, Wlin, blin, out, nN);
}

// round 15
// speedup vs baseline: 1.0696x; 1.0696x over previous
#include <cuda_runtime.h>
#include <cuda_bf16.h>

// Problem constants
#define CUR   512
#define HID   64
#define OUTD  64
#define HEADS 6
#define FTOT  (HEADS*OUTD)   // 384
#define CATD  (HID + FTOT)   // 448
#define NMAX  50000
#define EMAX  860000

// ---------------- device scratch ----------------
__device__ float g_h[(size_t)NMAX * HID];        // 12.8 MB (L2 resident)
__device__ float g_acc[(size_t)NMAX * FTOT];     // gathered, normalized
__device__ float g_asrc[(size_t)NMAX * HEADS];
__device__ float g_adst[(size_t)NMAX * HEADS];
__device__ float g_ws[HID * HEADS];              // W_gat_h @ att_src_h
__device__ float g_wd[HID * HEADS];
__device__ int   g_deg[NMAX];
__device__ int   g_cnt[NMAX];
__device__ int   g_off[NMAX + 1];
__device__ int   g_csrc[EMAX];
__device__ int   g_is64;

// ---------------- helpers ----------------
__device__ __forceinline__ void load_edge(const void* eidx, long E, long i,
                                          int& s, int& d) {
    if (g_is64) {
        const long long* p = (const long long*)eidx;
        s = (int)p[i];
        d = (int)p[E + i];
    } else {
        const int* p = (const int*)eidx;
        s = p[i];
        d = p[E + i];
    }
}

// int64 indices < 50000 => all high words zero over first 64 entries.
__global__ void k_detect(const int* e32) {
    int allzero = 1;
    for (int i = 1; i < 128; i += 2)
        if (e32[i] != 0) { allzero = 0; break; }
    g_is64 = allzero;
}

__global__ void k_zero(int nN) {
    int i = blockIdx.x * blockDim.x + threadIdx.x;
    if (i < nN) { g_deg[i] = 0; g_cnt[i] = 0; }
}

// ws[k][h] = sum_c W_gat[k, h*64+c] * att_src[h][c]   (and wd with att_dst)
__global__ void k_wsd(const float* __restrict__ Wg,
                      const float* __restrict__ as_,
                      const float* __restrict__ ad_) {
    int t = threadIdx.x;            // 0..383
    int h = t >> 6, k = t & 63;
    float s = 0.f, d = 0.f;
    #pragma unroll 8
    for (int c = 0; c < OUTD; c++) {
        float wv = Wg[k * FTOT + h * OUTD + c];
        s += wv * as_[h * OUTD + c];
        d += wv * ad_[h * OUTD + c];
    }
    g_ws[k * HEADS + h] = s;
    g_wd[k * HEADS + h] = d;
}

// ---------------- histogram of dst ----------------
__global__ void k_hist(const void* eidx, long E, long E2) {
    long i = (long)blockIdx.x * blockDim.x + threadIdx.x;
    if (i >= E2) return;
    int d;
    if (i < E) {
        if (g_is64) d = (int)((const long long*)eidx)[E + i];
        else        d = ((const int*)eidx)[E + i];
    } else d = (int)(i - E);
    atomicAdd(&g_deg[d], 1);
}

// ---------------- exclusive scan (single block) ----------------
__global__ void k_scan(int nN) {
    __shared__ int part[1024];
    int t = threadIdx.x;
    int chunk = (nN + 1023) / 1024;
    int lo = t * chunk;
    int hi = lo + chunk; if (hi > nN) hi = nN; if (lo > nN) lo = nN;
    int s = 0;
    for (int i = lo; i < hi; i++) s += g_deg[i];
    part[t] = s;
    __syncthreads();
    for (int o = 1; o < 1024; o <<= 1) {
        int v = 0;
        if (t >= o) v = part[t - o];
        __syncthreads();
        if (t >= o) part[t] += v;
        __syncthreads();
    }
    int run = (t > 0) ? part[t - 1] : 0;
    for (int i = lo; i < hi; i++) { g_off[i] = run; run += g_deg[i]; }
    if (t == 1023) g_off[nN] = part[1023];
}

__global__ void k_fill(const void* eidx, long E, long E2) {
    long i = (long)blockIdx.x * blockDim.x + threadIdx.x;
    if (i >= E2) return;
    int s, d;
    if (i < E) load_edge(eidx, E, i, s, d);
    else       s = d = (int)(i - E);
    int pos = g_off[d] + atomicAdd(&g_cnt[d], 1);
    g_csrc[pos] = s;
}

// ---------------- h = x @ W_pre + b_pre ----------------
// 32 rows/block; block (32,4) = 128 thr; each thread 2 cols x 8 rows
__global__ void __launch_bounds__(128, 3)
k_pre(const float* __restrict__ x, const float* __restrict__ W,
      const float* __restrict__ b, int nN) {
    __shared__ float xs[32][CUR];   // 64 KB
    int tx = threadIdx.x, ty = threadIdx.y;
    int tid = ty * 32 + tx;
    int row0 = blockIdx.x * 32;
    float4* xsv = (float4*)&xs[0][0];
    const int VROW = CUR / 4;  // 128
    for (int i = tid; i < 32 * VROW; i += 128) {
        int r = i / VROW, q = i % VROW;
        int rr = row0 + r;
        float4 v = make_float4(0.f, 0.f, 0.f, 0.f);
        if (rr < nN) v = ((const float4*)(x + (size_t)rr * CUR))[q];
        xsv[i] = v;
    }
    __syncthreads();
    int c0 = tx * 2;
    int r0 = ty * 8;
    float a0[8], a1[8];
    #pragma unroll
    for (int r = 0; r < 8; r++) { a0[r] = 0.f; a1[r] = 0.f; }
    #pragma unroll 2
    for (int k = 0; k < CUR; k += 4) {
        float2 w0 = *(const float2*)&W[(k + 0) * HID + c0];
        float2 w1 = *(const float2*)&W[(k + 1) * HID + c0];
        float2 w2 = *(const float2*)&W[(k + 2) * HID + c0];
        float2 w3 = *(const float2*)&W[(k + 3) * HID + c0];
        #pragma unroll
        for (int r = 0; r < 8; r++) {
            float4 v = *(float4*)&xs[r0 + r][k];
            a0[r] += v.x * w0.x + v.y * w1.x + v.z * w2.x + v.w * w3.x;
            a1[r] += v.x * w0.y + v.y * w1.y + v.z * w2.y + v.w * w3.y;
        }
    }
    float2 bb = *(const float2*)&b[c0];
    #pragma unroll
    for (int r = 0; r < 8; r++) {
        int rr = row0 + r0 + r;
        if (rr < nN) {
            float2 s = {a0[r] + bb.x, a1[r] + bb.y};
            *(float2*)&g_h[(size_t)rr * HID + c0] = s;
        }
    }
}

// ---------------- a_src / a_dst from h directly: warp per node ------------
__global__ void k_att2(int nN) {
    int n = blockIdx.x * (blockDim.x >> 5) + (threadIdx.x >> 5);
    if (n >= nN) return;
    int lane = threadIdx.x & 31;
    float h0 = g_h[(size_t)n * HID + lane];
    float h1v = g_h[(size_t)n * HID + 32 + lane];
    float sv[HEADS], dv[HEADS];
    #pragma unroll
    for (int h = 0; h < HEADS; h++) {
        sv[h] = h0 * g_ws[lane * HEADS + h] + h1v * g_ws[(lane + 32) * HEADS + h];
        dv[h] = h0 * g_wd[lane * HEADS + h] + h1v * g_wd[(lane + 32) * HEADS + h];
    }
    #pragma unroll
    for (int o = 16; o > 0; o >>= 1) {
        #pragma unroll
        for (int h = 0; h < HEADS; h++) {
            sv[h] += __shfl_xor_sync(0xffffffffu, sv[h], o);
            dv[h] += __shfl_xor_sync(0xffffffffu, dv[h], o);
        }
    }
    if (lane == 0) {
        #pragma unroll
        for (int h = 0; h < HEADS; h++) {
            g_asrc[n * HEADS + h] = sv[h];
            g_adst[n * HEADS + h] = dv[h];
        }
    }
}

// ---------------- CSR gather of h[src]: softmax-weighted, atomic-free -----
#define GW 8
__global__ void k_gather(int nN) {
    __shared__ float exs[GW][32][HEADS];
    int w = threadIdx.x >> 5;
    int n = blockIdx.x * GW + w;
    if (n >= nN) return;
    int lane = threadIdx.x & 31;
    int lo = g_off[n], hi = g_off[n + 1];

    float adv = (lane < HEADS) ? g_adst[n * HEADS + lane] : 0.f;
    float adn[HEADS];
    #pragma unroll
    for (int h = 0; h < HEADS; h++) adn[h] = __shfl_sync(0xffffffffu, adv, h);

    float mx[HEADS];
    #pragma unroll
    for (int h = 0; h < HEADS; h++) mx[h] = -1e30f;
    for (int j = lo + lane; j < hi; j += 32) {
        int s = g_csrc[j];
        const float2* ap = (const float2*)&g_asrc[s * HEADS];
        float2 a01 = ap[0], a23 = ap[1], a45 = ap[2];
        float av[HEADS] = {a01.x, a01.y, a23.x, a23.y, a45.x, a45.y};
        #pragma unroll
        for (int h = 0; h < HEADS; h++) {
            float a = av[h] + adn[h];
            a = (a > 0.f) ? a : 0.2f * a;
            mx[h] = fmaxf(mx[h], a);
        }
    }
    #pragma unroll
    for (int h = 0; h < HEADS; h++)
        #pragma unroll
        for (int o = 16; o > 0; o >>= 1)
            mx[h] = fmaxf(mx[h], __shfl_xor_sync(0xffffffffu, mx[h], o));

    float acc[2 * HEADS];
    #pragma unroll
    for (int q = 0; q < 2 * HEADS; q++) acc[q] = 0.f;
    float den[HEADS];
    #pragma unroll
    for (int h = 0; h < HEADS; h++) den[h] = 0.f;

    for (int base = lo; base < hi; base += 32) {
        int j = base + lane;
        int s = 0;
        if (j < hi) {
            s = g_csrc[j];
            const float2* ap = (const float2*)&g_asrc[s * HEADS];
            float2 a01 = ap[0], a23 = ap[1], a45 = ap[2];
            float av[HEADS] = {a01.x, a01.y, a23.x, a23.y, a45.x, a45.y};
            #pragma unroll
            for (int h = 0; h < HEADS; h++) {
                float a = av[h] + adn[h];
                a = (a > 0.f) ? a : 0.2f * a;
                float ex = __expf(a - mx[h]);
                den[h] += ex;
                exs[w][lane][h] = ex;
            }
        }
        __syncwarp();
        int cnt = hi - base; if (cnt > 32) cnt = 32;
        for (int e = 0; e < cnt; e++) {
            int se = __shfl_sync(0xffffffffu, s, e);
            float2 hv = ((const float2*)(g_h + (size_t)se * HID))[lane];
            #pragma unroll
            for (int h = 0; h < HEADS; h++) {
                float ex = exs[w][e][h];
                acc[2 * h + 0] += ex * hv.x;
                acc[2 * h + 1] += ex * hv.y;
            }
        }
        __syncwarp();
    }

    #pragma unroll
    for (int h = 0; h < HEADS; h++)
        #pragma unroll
        for (int o = 16; o > 0; o >>= 1)
            den[h] += __shfl_xor_sync(0xffffffffu, den[h], o);

    #pragma unroll
    for (int h = 0; h < HEADS; h++) {
        float inv = 1.f / den[h];
        float2 st;
        st.x = acc[2 * h + 0] * inv;
        st.y = acc[2 * h + 1] * inv;
        ((float2*)(g_acc + (size_t)n * FTOT + h * OUTD))[lane] = st;
    }
}

// ---------------- fused: h1 = leakyrelu(acc@Wg + bg); out = [h,h1]@Wl + bl
__global__ void __launch_bounds__(384, 2)
k_out(const float* __restrict__ Wg, const float* __restrict__ bg,
      const float* __restrict__ Wl, const float* __restrict__ bl,
      float* __restrict__ out, int nN) {
    __shared__ float as[16][FTOT];   // acc tile
    __shared__ float cat[16][CATD];  // [h | h1] tile
    int t = threadIdx.x;             // 0..383
    int row0 = blockIdx.x * 16;

    // stage 1: load acc tile + h tile
    float4* asv = (float4*)&as[0][0];
    const int AV = FTOT / 4;  // 96
    for (int i = t; i < 16 * AV; i += 384) {
        int r = i / AV, q = i % AV;
        int rr = row0 + r;
        float4 v = make_float4(0.f, 0.f, 0.f, 0.f);
        if (rr < nN) v = ((const float4*)(g_acc + (size_t)rr * FTOT))[q];
        asv[i] = v;
    }
    const int HV = HID / 4;   // 16
    for (int i = t; i < 16 * HV; i += 384) {
        int r = i / HV, q = i % HV;
        int rr = row0 + r;
        float4 v = make_float4(0.f, 0.f, 0.f, 0.f);
        if (rr < nN) v = ((const float4*)(g_h + (size_t)rr * HID))[q];
        *(float4*)&cat[r][q * 4] = v;
    }
    __syncthreads();

    // stage 2: each thread 2 cols x 8 rows of h1 -> cat[r][HID+c]
    {
        int pc = t % 192;
        int c0 = pc * 2;                 // col pair (same head: c0 even, 64 even)
        int rg8 = (t / 192) * 8;         // rows rg8..rg8+7
        int kb = (c0 >> 6) * OUTD;       // head offset into acc row
        float h1a0[8], h1a1[8];
        #pragma unroll
        for (int r = 0; r < 8; r++) { h1a0[r] = 0.f; h1a1[r] = 0.f; }
        #pragma unroll
        for (int kc = 0; kc < HID; kc += 8) {
            float2 wreg[8];
            #pragma unroll
            for (int k = 0; k < 8; k++)
                wreg[k] = *(const float2*)&Wg[(kc + k) * FTOT + c0];
            #pragma unroll
            for (int r = 0; r < 8; r++) {
                #pragma unroll
                for (int k = 0; k < 8; k += 4) {
                    float4 v = *(float4*)&as[rg8 + r][kb + kc + k];
                    h1a0[r] += v.x * wreg[k].x + v.y * wreg[k + 1].x
                             + v.z * wreg[k + 2].x + v.w * wreg[k + 3].x;
                    h1a1[r] += v.x * wreg[k].y + v.y * wreg[k + 1].y
                             + v.z * wreg[k + 2].y + v.w * wreg[k + 3].y;
                }
            }
        }
        float2 bb2 = *(const float2*)&bg[c0];
        #pragma unroll
        for (int r = 0; r < 8; r++) {
            float v0 = h1a0[r] + bb2.x;
            float v1 = h1a1[r] + bb2.y;
            float2 s;
            s.x = (v0 > 0.f) ? v0 : 0.01f * v0;
            s.y = (v1 > 0.f) ? v1 : 0.01f * v1;
            *(float2*)&cat[rg8 + r][HID + c0] = s;
        }
    }
    __syncthreads();

    // stage 3: out = cat @ Wl + bl; thread t -> col = t&63, rows rg, rg+6, rg+12
    {
        int col = t & 63, rg = t >> 6;
        float ac0 = 0.f, ac1 = 0.f, ac2 = 0.f;
        int r1 = rg + 6, r2 = rg + 12;
        #pragma unroll 4
        for (int k = 0; k < CATD; k += 4) {
            float w0 = Wl[(k + 0) * OUTD + col];
            float w1 = Wl[(k + 1) * OUTD + col];
            float w2 = Wl[(k + 2) * OUTD + col];
            float w3 = Wl[(k + 3) * OUTD + col];
            float4 v0 = *(float4*)&cat[rg][k];
            ac0 += v0.x * w0 + v0.y * w1 + v0.z * w2 + v0.w * w3;
            float4 v1 = *(float4*)&cat[r1][k];
            ac1 += v1.x * w0 + v1.y * w1 + v1.z * w2 + v1.w * w3;
            if (r2 < 16) {
                float4 v2 = *(float4*)&cat[r2][k];
                ac2 += v2.x * w0 + v2.y * w1 + v2.z * w2 + v2.w * w3;
            }
        }
        float bb = bl[col];
        int rr0 = row0 + rg, rr1 = row0 + r1, rr2 = row0 + r2;
        if (rr0 < nN)             out[(size_t)rr0 * OUTD + col] = ac0 + bb;
        if (rr1 < nN)             out[(size_t)rr1 * OUTD + col] = ac1 + bb;
        if (r2 < 16 && rr2 < nN)  out[(size_t)rr2 * OUTD + col] = ac2 + bb;
    }
}

// ---------------- launch ----------------
extern "C" void kernel_launch(void* const* d_in, const int* in_sizes, int n_in,
                              void* d_out, int out_size) {
    const float* x    = (const float*)d_in[0];
    const void*  eidx = d_in[1];
    const float* Wpre = (const float*)d_in[3];
    const float* bpre = (const float*)d_in[4];
    const float* Wgat = (const float*)d_in[5];
    const float* atts = (const float*)d_in[6];
    const float* attd = (const float*)d_in[7];
    const float* bgat = (const float*)d_in[8];
    const float* Wlin = (const float*)d_in[9];
    const float* blin = (const float*)d_in[10];
    float* out = (float*)d_out;

    int  nN = in_sizes[0] / CUR;
    long E  = (long)in_sizes[1] / 2;
    long E2 = E + nN;

    k_detect<<<1, 1>>>((const int*)eidx);
    k_zero<<<(nN + 255) / 256, 256>>>(nN);
    k_wsd<<<1, 384>>>(Wgat, atts, attd);
    k_pre<<<(nN + 31) / 32, dim3(32, 4)>>>(x, Wpre, bpre, nN);
    k_att2<<<(nN + 7) / 8, 256>>>(nN);
    k_hist<<<(int)((E2 + 255) / 256), 256>>>(eidx, E, E2);
    k_scan<<<1, 1024>>>(nN);
    k_fill<<<(int)((E2 + 255) / 256), 256>>>(eidx, E, E2);
    k_gather<<<(nN + GW - 1) / GW, GW * 32>>>(nN);
    k_out<<<(nN + 15) / 16, 384>>>(Wgat, bgat, Wlin, blin, out, nN);
}